// round 2
// baseline (speedup 1.0000x reference)
#include <cuda_runtime.h>
#include <math.h>

// Problem constants (fixed by the dataset)
#define NB 256      // batch (docs)
#define NL 512      // tokens per doc
#define ND 1024     // embedding dim
// emb_table is (V+1, D) = (50001, 1024) float32

// Scratch (device globals — no allocation allowed)
__device__ float g_hpart[NB * 4 * ND];  // per-doc 4-way partial sums of emb rows
__device__ float g_v[NB * ND];          // v[b] = W_b @ mean(emb[b])

// ---------------------------------------------------------------------------
// Pass 1: partial sums of gathered embedding rows.
// Grid: 1024 CTAs (4 per doc, 128 tokens each), 256 threads, float4/thread.
// Docs ascending => tail (high b) rows are L2-resident when pass 2 starts.
// ---------------------------------------------------------------------------
__global__ void k_hidden(const int* __restrict__ tokens,
                         const float* __restrict__ emb) {
    __shared__ int s_tok[128];
    const int b    = blockIdx.x >> 2;
    const int part = blockIdx.x & 3;
    const int t    = threadIdx.x;

    if (t < 128) s_tok[t] = tokens[b * NL + part * 128 + t] + 1;
    __syncthreads();

    const float4* emb4 = reinterpret_cast<const float4*>(emb);
    float4 acc = make_float4(0.f, 0.f, 0.f, 0.f);

#pragma unroll 8
    for (int l = 0; l < 128; ++l) {
        const int row = s_tok[l];
        float4 e = __ldg(&emb4[(size_t)row * 256 + t]);
        acc.x += e.x; acc.y += e.y; acc.z += e.z; acc.w += e.w;
    }
    reinterpret_cast<float4*>(g_hpart)[(size_t)blockIdx.x * 256 + t] = acc;
}

// ---------------------------------------------------------------------------
// Small GEMM: v[b,n] = sum_e hidden[b,e] * W[n,e],  hidden = (p0+..+p3)/512.
// M=256, N=1024, K=1024. Tiles BM=32, BN=64, BK=32; 256 threads; 2x4 microtile.
// Grid: (N/64, M/32) = (16, 8) = 128 CTAs.
// ---------------------------------------------------------------------------
__global__ void k_v(const float* __restrict__ W) {
    __shared__ float sA[32 * 34];   // [k][m], pad to 34
    __shared__ float sB[32 * 68];   // [k][n], pad to 68

    const int tid = threadIdx.x;
    const int bn0 = blockIdx.x * 64;
    const int bm0 = blockIdx.y * 32;
    const int tx  = tid & 15;       // n: 4 outputs
    const int ty  = tid >> 4;       // m: 2 outputs
    const int lm  = tid >> 3;       // 0..31
    const int lk  = tid & 7;        // 0..7 float4 groups along k

    const float4* W4  = reinterpret_cast<const float4*>(W);
    const float4* hp4 = reinterpret_cast<const float4*>(g_hpart);

    float acc[2][4] = {{0.f,0.f,0.f,0.f},{0.f,0.f,0.f,0.f}};

    for (int k0 = 0; k0 < 1024; k0 += 32) {
        // Load A tile: fuse 4-way partial-sum + mean scale
        {
            const int bb = bm0 + lm;
            const int f  = (k0 >> 2) + lk;
            float4 h0 = hp4[(size_t)(bb * 4 + 0) * 256 + f];
            float4 h1 = hp4[(size_t)(bb * 4 + 1) * 256 + f];
            float4 h2 = hp4[(size_t)(bb * 4 + 2) * 256 + f];
            float4 h3 = hp4[(size_t)(bb * 4 + 3) * 256 + f];
            const float s = 1.0f / 512.0f;
            sA[(lk * 4 + 0) * 34 + lm] = (h0.x + h1.x + h2.x + h3.x) * s;
            sA[(lk * 4 + 1) * 34 + lm] = (h0.y + h1.y + h2.y + h3.y) * s;
            sA[(lk * 4 + 2) * 34 + lm] = (h0.z + h1.z + h2.z + h3.z) * s;
            sA[(lk * 4 + 3) * 34 + lm] = (h0.w + h1.w + h2.w + h3.w) * s;
        }
        // Load B tile (W rows are k-contiguous)
#pragma unroll
        for (int r = 0; r < 2; ++r) {
            const int n = lm + r * 32;
            float4 w = W4[(size_t)(bn0 + n) * 256 + (k0 >> 2) + lk];
            sB[(lk * 4 + 0) * 68 + n] = w.x;
            sB[(lk * 4 + 1) * 68 + n] = w.y;
            sB[(lk * 4 + 2) * 68 + n] = w.z;
            sB[(lk * 4 + 3) * 68 + n] = w.w;
        }
        __syncthreads();

#pragma unroll
        for (int k = 0; k < 32; ++k) {
            float2 a2 = *reinterpret_cast<const float2*>(&sA[k * 34 + ty * 2]);
            float4 b4 = *reinterpret_cast<const float4*>(&sB[k * 68 + tx * 4]);
            acc[0][0] += a2.x * b4.x; acc[0][1] += a2.x * b4.y;
            acc[0][2] += a2.x * b4.z; acc[0][3] += a2.x * b4.w;
            acc[1][0] += a2.y * b4.x; acc[1][1] += a2.y * b4.y;
            acc[1][2] += a2.y * b4.z; acc[1][3] += a2.y * b4.w;
        }
        __syncthreads();
    }

#pragma unroll
    for (int i = 0; i < 2; ++i) {
        const int row = bm0 + ty * 2 + i;
        float4 o = make_float4(acc[i][0], acc[i][1], acc[i][2], acc[i][3]);
        reinterpret_cast<float4*>(g_v)[row * 256 + (bn0 >> 2) + tx] = o;
    }
}

// ---------------------------------------------------------------------------
// Pass 2: per-doc online softmax + weighted context, single read of each row.
// 1 CTA per doc, 256 threads = 8 warps, each warp owns 64 tokens with a
// warp-private (m, den, n[1024]) flash state; cross-warp combine via SMEM.
// Docs iterated in REVERSE so pass-1's L2-resident tail is hit first.
// ---------------------------------------------------------------------------
__global__ void __launch_bounds__(256, 2)
k_ct(const int* __restrict__ tokens, const float* __restrict__ emb,
     float* __restrict__ out) {
    __shared__ int   s_tok[512];
    __shared__ float s_ct[1024];
    __shared__ float s_m[8];
    __shared__ float s_d[8];

    const int b    = (NB - 1) - blockIdx.x;   // reverse order for L2 priming
    const int tid  = threadIdx.x;
    const int w    = tid >> 5;
    const int lane = tid & 31;

    s_tok[tid]       = tokens[b * NL + tid] + 1;
    s_tok[tid + 256] = tokens[b * NL + tid + 256] + 1;
    reinterpret_cast<float4*>(s_ct)[tid] = make_float4(0.f, 0.f, 0.f, 0.f);
    __syncthreads();

    const float4* emb4 = reinterpret_cast<const float4*>(emb);
    const float4* v4   = reinterpret_cast<const float4*>(g_v);

    // lane owns D-components d = it*128 + lane*4 .. +3, it = 0..7
    float4 vr[8];
#pragma unroll
    for (int it = 0; it < 8; ++it) vr[it] = v4[b * 256 + it * 32 + lane];

    float4 nacc[8];
#pragma unroll
    for (int it = 0; it < 8; ++it) nacc[it] = make_float4(0.f, 0.f, 0.f, 0.f);

    float m   = -INFINITY;
    float den = 0.f;

    for (int j = 0; j < 64; ++j) {
        const int row = s_tok[w * 64 + j];
        const float4* p = emb4 + (size_t)row * 256 + lane;

        float4 e[8];
        float  s = 0.f;
#pragma unroll
        for (int it = 0; it < 8; ++it) {
            e[it] = p[it * 32];
            s += e[it].x * vr[it].x + e[it].y * vr[it].y
               + e[it].z * vr[it].z + e[it].w * vr[it].w;
        }
#pragma unroll
        for (int o = 16; o; o >>= 1) s += __shfl_xor_sync(0xffffffffu, s, o);

        const float m_new = fmaxf(m, s);
        const float c  = __expf(m - m_new);   // 1 when max unchanged, 0 first iter
        const float wl = __expf(s - m_new);
        den = den * c + wl;
        if (c != 1.0f) {
#pragma unroll
            for (int it = 0; it < 8; ++it) {
                nacc[it].x *= c; nacc[it].y *= c;
                nacc[it].z *= c; nacc[it].w *= c;
            }
        }
#pragma unroll
        for (int it = 0; it < 8; ++it) {
            nacc[it].x += wl * e[it].x; nacc[it].y += wl * e[it].y;
            nacc[it].z += wl * e[it].z; nacc[it].w += wl * e[it].w;
        }
        m = m_new;
    }

    if (lane == 0) { s_m[w] = m; s_d[w] = den; }
    __syncthreads();

    float M = -INFINITY;
#pragma unroll
    for (int i = 0; i < 8; ++i) M = fmaxf(M, s_m[i]);
    float dg = 0.f;
#pragma unroll
    for (int i = 0; i < 8; ++i) dg += s_d[i] * __expf(s_m[i] - M);

    const float sc = __expf(m - M) / dg;
#pragma unroll
    for (int it = 0; it < 8; ++it) {
        const int d0 = it * 128 + lane * 4;
        atomicAdd(&s_ct[d0 + 0], nacc[it].x * sc);
        atomicAdd(&s_ct[d0 + 1], nacc[it].y * sc);
        atomicAdd(&s_ct[d0 + 2], nacc[it].z * sc);
        atomicAdd(&s_ct[d0 + 3], nacc[it].w * sc);
    }
    __syncthreads();

    reinterpret_cast<float4*>(out)[b * 256 + tid] =
        reinterpret_cast<float4*>(s_ct)[tid];
}

// ---------------------------------------------------------------------------
extern "C" void kernel_launch(void* const* d_in, const int* in_sizes, int n_in,
                              void* d_out, int out_size) {
    const int*   tokens = (const int*)d_in[0];
    // d_in[1] = max_len (scalar, unused — fixed at 512)
    const float* emb    = (const float*)d_in[2];
    const float* W      = (const float*)d_in[3];
    float*       out    = (float*)d_out;

    k_hidden<<<NB * 4, 256>>>(tokens, emb);
    k_v<<<dim3(16, 8), 256>>>(W);
    k_ct<<<NB, 256>>>(tokens, emb, out);
}

// round 3
// speedup vs baseline: 1.2079x; 1.2079x over previous
#include <cuda_runtime.h>
#include <math.h>

// Problem constants (fixed by the dataset)
#define NB 256      // batch (docs)
#define NL 512      // tokens per doc
#define ND 1024     // embedding dim
// emb_table is (V+1, D) = (50001, 1024) float32

// Scratch (device globals — no allocation allowed)
__device__ float g_hpart[NB * 2 * ND];  // per-doc 2-way partial sums of emb rows
__device__ float g_v[NB * ND];          // v[b] = W_b @ mean(emb[b])

typedef unsigned long long u64;

// ---------------------------------------------------------------------------
// Pass 1: partial sums of gathered embedding rows.  (EXACT R1 version)
// Grid: 512 CTAs (2 per doc, 256 tokens each), 256 threads, float4 per thread.
// ---------------------------------------------------------------------------
__global__ void k_hidden(const int* __restrict__ tokens,
                         const float* __restrict__ emb) {
    __shared__ int s_tok[256];
    const int b    = blockIdx.x >> 1;
    const int part = blockIdx.x & 1;
    const int t    = threadIdx.x;

    s_tok[t] = tokens[b * NL + part * 256 + t] + 1;   // +1 per reference lookup
    __syncthreads();

    const float4* emb4 = reinterpret_cast<const float4*>(emb);
    float4 acc = make_float4(0.f, 0.f, 0.f, 0.f);

#pragma unroll 4
    for (int l = 0; l < 256; ++l) {
        const int row = s_tok[l];
        float4 e = __ldg(&emb4[(size_t)row * 256 + t]);
        acc.x += e.x; acc.y += e.y; acc.z += e.z; acc.w += e.w;
    }
    reinterpret_cast<float4*>(g_hpart)[(b * 2 + part) * 256 + t] = acc;
}

// ---------------------------------------------------------------------------
// Small GEMM with packed f32x2 FMA (sm_100+ FFMA2):
// v[b,n] = sum_e hidden[b,e] * W[n,e],  hidden = (p0+p1)/512.
// M=256, N=1024, K=1024. BM=32, BN=64, BK=32; 256 threads; 2m x 4n microtile
// computed as 2m x 2 packed-f32x2. Grid (16, 8) = 128 CTAs.
// ---------------------------------------------------------------------------
__device__ __forceinline__ u64 fma2(u64 a, u64 b, u64 c) {
    u64 d;
    asm("fma.rn.f32x2 %0, %1, %2, %3;" : "=l"(d) : "l"(a), "l"(b), "l"(c));
    return d;
}

__global__ void k_v(const float* __restrict__ W) {
    __shared__ float2 sAd[32 * 33];   // [k][m] duplicated (a,a) pairs, pad 33
    __shared__ float  sB[32 * 68];    // [k][n], pad to 68 (float4-aligned)

    const int tid = threadIdx.x;
    const int bn0 = blockIdx.x * 64;
    const int bm0 = blockIdx.y * 32;
    const int tx  = tid & 15;       // n: 4 outputs (2 x f32x2)
    const int ty  = tid >> 4;       // m: 2 outputs
    const int lm  = tid >> 3;       // 0..31
    const int lk  = tid & 7;        // 0..7 float4 groups along k

    const float4* W4  = reinterpret_cast<const float4*>(W);
    const float4* hp4 = reinterpret_cast<const float4*>(g_hpart);

    u64 acc[2][2];
    {
        u64 z = 0;   // bit pattern of (0.f, 0.f)
        acc[0][0] = z; acc[0][1] = z; acc[1][0] = z; acc[1][1] = z;
    }

    for (int k0 = 0; k0 < 1024; k0 += 32) {
        // Load A tile: fuse partial-sum + mean scale, store duplicated pairs
        {
            const int bb = bm0 + lm;
            float4 h0 = hp4[bb * 512 +       (k0 >> 2) + lk];
            float4 h1 = hp4[bb * 512 + 256 + (k0 >> 2) + lk];
            const float s = 1.0f / 512.0f;
            float a0 = (h0.x + h1.x) * s;
            float a1 = (h0.y + h1.y) * s;
            float a2 = (h0.z + h1.z) * s;
            float a3 = (h0.w + h1.w) * s;
            sAd[(lk * 4 + 0) * 33 + lm] = make_float2(a0, a0);
            sAd[(lk * 4 + 1) * 33 + lm] = make_float2(a1, a1);
            sAd[(lk * 4 + 2) * 33 + lm] = make_float2(a2, a2);
            sAd[(lk * 4 + 3) * 33 + lm] = make_float2(a3, a3);
        }
        // Load B tile (W rows are k-contiguous)
#pragma unroll
        for (int r = 0; r < 2; ++r) {
            const int n = lm + r * 32;
            float4 w = W4[(size_t)(bn0 + n) * 256 + (k0 >> 2) + lk];
            sB[(lk * 4 + 0) * 68 + n] = w.x;
            sB[(lk * 4 + 1) * 68 + n] = w.y;
            sB[(lk * 4 + 2) * 68 + n] = w.z;
            sB[(lk * 4 + 3) * 68 + n] = w.w;
        }
        __syncthreads();

#pragma unroll
        for (int k = 0; k < 32; ++k) {
            u64 A0 = *reinterpret_cast<const u64*>(&sAd[k * 33 + ty * 2 + 0]);
            u64 A1 = *reinterpret_cast<const u64*>(&sAd[k * 33 + ty * 2 + 1]);
            const u64* pB = reinterpret_cast<const u64*>(&sB[k * 68 + tx * 4]);
            u64 Bx = pB[0];
            u64 By = pB[1];
            acc[0][0] = fma2(A0, Bx, acc[0][0]);
            acc[0][1] = fma2(A0, By, acc[0][1]);
            acc[1][0] = fma2(A1, Bx, acc[1][0]);
            acc[1][1] = fma2(A1, By, acc[1][1]);
        }
        __syncthreads();
    }

#pragma unroll
    for (int i = 0; i < 2; ++i) {
        const int row = bm0 + ty * 2 + i;
        float2 lo = *reinterpret_cast<float2*>(&acc[i][0]);
        float2 hi = *reinterpret_cast<float2*>(&acc[i][1]);
        float4 o = make_float4(lo.x, lo.y, hi.x, hi.y);
        reinterpret_cast<float4*>(g_v)[row * 256 + (bn0 >> 2) + tx] = o;
    }
}

// ---------------------------------------------------------------------------
// Pass 2: per-doc online softmax + weighted context.  (EXACT R1 version)
// 1 CTA per doc, 512 threads = 16 warps, each warp owns 32 tokens with a
// warp-private (m, den, n[1024]) flash state; cross-warp combine via SMEM.
// ---------------------------------------------------------------------------
__global__ void __launch_bounds__(512, 1)
k_ct(const int* __restrict__ tokens, const float* __restrict__ emb,
     float* __restrict__ out) {
    __shared__ int   s_tok[512];
    __shared__ float s_ct[1024];
    __shared__ float s_m[16];
    __shared__ float s_d[16];

    const int b    = blockIdx.x;
    const int tid  = threadIdx.x;
    const int w    = tid >> 5;
    const int lane = tid & 31;

    s_tok[tid]       = tokens[b * NL + tid] + 1;
    s_ct[tid]        = 0.f;
    s_ct[tid + 512]  = 0.f;
    __syncthreads();

    const float4* emb4 = reinterpret_cast<const float4*>(emb);
    const float4* v4   = reinterpret_cast<const float4*>(g_v);

    // lane owns D-components d = it*128 + lane*4 .. +3, it = 0..7
    float4 vr[8];
#pragma unroll
    for (int it = 0; it < 8; ++it) vr[it] = v4[b * 256 + it * 32 + lane];

    float4 nacc[8];
#pragma unroll
    for (int it = 0; it < 8; ++it) nacc[it] = make_float4(0.f, 0.f, 0.f, 0.f);

    float m   = -INFINITY;
    float den = 0.f;

    for (int j = 0; j < 32; ++j) {
        const int row = s_tok[w * 32 + j];
        const float4* p = emb4 + (size_t)row * 256 + lane;

        float4 e[8];
        float  s = 0.f;
#pragma unroll
        for (int it = 0; it < 8; ++it) {
            e[it] = p[it * 32];
            s += e[it].x * vr[it].x + e[it].y * vr[it].y
               + e[it].z * vr[it].z + e[it].w * vr[it].w;
        }
#pragma unroll
        for (int o = 16; o; o >>= 1) s += __shfl_xor_sync(0xffffffffu, s, o);

        const float m_new = fmaxf(m, s);
        const float c  = __expf(m - m_new);   // 1 when max unchanged, 0 on first
        const float wl = __expf(s - m_new);
        den = den * c + wl;
        if (c != 1.0f) {
#pragma unroll
            for (int it = 0; it < 8; ++it) {
                nacc[it].x *= c; nacc[it].y *= c;
                nacc[it].z *= c; nacc[it].w *= c;
            }
        }
#pragma unroll
        for (int it = 0; it < 8; ++it) {
            nacc[it].x += wl * e[it].x; nacc[it].y += wl * e[it].y;
            nacc[it].z += wl * e[it].z; nacc[it].w += wl * e[it].w;
        }
        m = m_new;
    }

    if (lane == 0) { s_m[w] = m; s_d[w] = den; }
    __syncthreads();

    float M = -INFINITY;
#pragma unroll
    for (int i = 0; i < 16; ++i) M = fmaxf(M, s_m[i]);
    float dg = 0.f;
#pragma unroll
    for (int i = 0; i < 16; ++i) dg += s_d[i] * __expf(s_m[i] - M);

    const float sc = __expf(m - M) / dg;
#pragma unroll
    for (int it = 0; it < 8; ++it) {
        const int d0 = it * 128 + lane * 4;
        atomicAdd(&s_ct[d0 + 0], nacc[it].x * sc);
        atomicAdd(&s_ct[d0 + 1], nacc[it].y * sc);
        atomicAdd(&s_ct[d0 + 2], nacc[it].z * sc);
        atomicAdd(&s_ct[d0 + 3], nacc[it].w * sc);
    }
    __syncthreads();

    out[b * ND + tid]       = s_ct[tid];
    out[b * ND + tid + 512] = s_ct[tid + 512];
}

// ---------------------------------------------------------------------------
extern "C" void kernel_launch(void* const* d_in, const int* in_sizes, int n_in,
                              void* d_out, int out_size) {
    const int*   tokens = (const int*)d_in[0];
    // d_in[1] = max_len (scalar, unused — fixed at 512)
    const float* emb    = (const float*)d_in[2];
    const float* W      = (const float*)d_in[3];
    float*       out    = (float*)d_out;

    k_hidden<<<NB * 2, 256>>>(tokens, emb);
    k_v<<<dim3(16, 8), 256>>>(W);
    k_ct<<<NB, 512>>>(tokens, emb, out);
}